// round 13
// baseline (speedup 1.0000x reference)
#include <cuda_runtime.h>
#include <cuda_bf16.h>
#include <cstdint>

// Problem-fixed shapes: B=4, C=256, Ch=128, H=W=64 -> N=4096
#define NPIX 4096

// ---------------- scratch (no allocations allowed -> __device__ global) ----
#define OFF_T  0
#define OFF_F  2097152
#define OFF_G  4194304
#define OFF_H  6291456
#define OFF_PM 10485760
#define OFF_PS 11010048
#define OFF_FM 11534336
#define OFF_FS 11550720
#define OFF_T2 11567104
#define SCRATCH_FLOATS (11567104 + 2097152)

static __device__ float g_scratch[SCRATCH_FLOATS];

#define PK_BATCH 262144   // 4096*64 words per batch per plane
#define PK_PLANE 1048576  // 4 batches

// ---------------------------------------------------------------------------
__device__ __forceinline__ unsigned packbf(float x, float y) {
    __nv_bfloat162 t = __floats2bfloat162_rn(x, y);   // .x = low half
    return reinterpret_cast<unsigned&>(t);
}
__device__ __forceinline__ float bfhi(float x) {
    return __bfloat162float(__float2bfloat16(x));
}
__device__ __forceinline__ void ldsm4(unsigned& r0, unsigned& r1,
                                      unsigned& r2, unsigned& r3, unsigned a) {
    asm volatile("ldmatrix.sync.aligned.m8n8.x4.shared.b16 {%0,%1,%2,%3}, [%4];"
                 : "=r"(r0), "=r"(r1), "=r"(r2), "=r"(r3) : "r"(a));
}
__device__ __forceinline__ void cp16(unsigned dst, const void* src) {
    asm volatile("cp.async.cg.shared.global [%0], [%1], 16;"
                 :: "r"(dst), "l"(src));
}

#define MMA_BF16(c, a, b)                                                    \
    asm volatile(                                                            \
        "mma.sync.aligned.m16n8k16.row.col.f32.bf16.bf16.f32 "               \
        "{%0,%1,%2,%3},{%4,%5,%6,%7},{%8,%9},{%0,%1,%2,%3};"                 \
        : "+f"(c[0]), "+f"(c[1]), "+f"(c[2]), "+f"(c[3])                     \
        : "r"(a[0]), "r"(a[1]), "r"(a[2]), "r"(a[3]), "r"(b[0]), "r"(b[1]))

// ---------------------------------------------------------------------------
// Generic bf16 tensor-core GEMM (projections + final).
//   MODE 0: relu(acc+bias)  1: acc+bias
//        2: final (B scaled by inv[col] at staging, streaming ld/st of e and
//           normalized writeback to eWr; out = gamma*acc + res)
//        4: bias-add then write packed bf16 hi/lo pair-words (attn operands)
// ---------------------------------------------------------------------------
template <int BM, int ACM, int SPLIT, int MODE, int DUAL>
__global__ __launch_bounds__(BM * 2)
void mma_gemm(const float* __restrict__ A, const float* __restrict__ A2,
              size_t aStride, int lda,
              const float* __restrict__ X, const float* __restrict__ X2,
              size_t xStride,
              const float* __restrict__ bias, const float* __restrict__ bias2,
              const float* __restrict__ resAll,
              const float* __restrict__ gamma,
              float* __restrict__ C, float* __restrict__ C2,
              size_t cStride, int K,
              float* __restrict__ eWr,
              unsigned* __restrict__ Pkh, unsigned* __restrict__ Pkh2,
              unsigned* __restrict__ Pkl, unsigned* __restrict__ Pkl2)
{
    constexpr int AW = BM * 12;
    constexpr int BW = 128 * 12;
    constexpr int KPT = 1024 / BM;

    extern __shared__ unsigned smw[];
    unsigned* Ahw = smw;
    unsigned* Bhw = smw + AW;
    unsigned* Alw = (SPLIT == 3) ? (smw + AW + BW) : smw;
    unsigned* Blw = (SPLIT == 3) ? (smw + AW + BW + AW) : smw;

    const int z = blockIdx.z;
    const float* Asel = A;
    const float* Xsel = X;
    const float* bsel = bias;
    float*       Csel = C;
    unsigned*    PhSel = Pkh;
    unsigned*    PlSel = Pkl;
    if (DUAL && blockIdx.y == 1) {
        Asel = A2; Xsel = X2; bsel = bias2; Csel = C2; PhSel = Pkh2; PlSel = Pkl2;
    }

    const float* Ab = Asel + (size_t)z * aStride;
    const float* Xb = Xsel + (size_t)z * xStride;
    float*       Cb = Csel ? Csel + (size_t)z * cStride : (float*)nullptr;
    float*       eWrB = (MODE == 2) ? (eWr + (size_t)z * xStride) : (float*)nullptr;
    unsigned*    PhB = (MODE == 4) ? PhSel + (size_t)z * PK_BATCH : (unsigned*)nullptr;
    unsigned*    PlB = (MODE == 4) ? PlSel + (size_t)z * PK_BATCH : (unsigned*)nullptr;

    const int m0   = DUAL ? 0 : blockIdx.y * BM;
    const int n0   = blockIdx.x * 128;
    const int t    = threadIdx.x;
    const int lane = t & 31;
    const int warp = t >> 5;
    const int wm   = (warp >> 2) * 64;
    const int wn   = (warp & 3) * 32;
    const int tig  = lane & 3;

    const int nB   = t & 127;
    const int kbB  = (t >> 7) * KPT;
    const int mA0  = t >> 1;
    const int kshA = (t & 1) * 8;
    const int mA1  = t & (BM - 1);
    const int kbA  = (t >= BM) ? 8 : 0;

    const unsigned AhB = (unsigned)__cvta_generic_to_shared(Ahw);
    const unsigned AlB = (unsigned)__cvta_generic_to_shared(Alw);
    const unsigned BhB = (unsigned)__cvta_generic_to_shared(Bhw);
    const unsigned BlB = (unsigned)__cvta_generic_to_shared(Blw);
    const int aRow = ((lane >> 3) & 1) * 8 + (lane & 7);
    const int aKh  = (lane >> 4) * 4;
    const int bRow = (lane >> 4) * 8 + (lane & 7);
    const int bKh  = ((lane >> 3) & 1) * 4;
    unsigned aAH[4], aAL[4], bAH[2], bAL[2];
#pragma unroll
    for (int mt = 0; mt < 4; mt++) {
        const unsigned w = (unsigned)((wm + mt * 16 + aRow) * 12 + aKh) * 4u;
        aAH[mt] = AhB + w;
        aAL[mt] = AlB + w;
    }
#pragma unroll
    for (int p = 0; p < 2; p++) {
        const unsigned w = (unsigned)((wn + p * 16 + bRow) * 12 + bKh) * 4u;
        bAH[p] = BhB + w;
        bAL[p] = BlB + w;
    }

    const float inv_n = (MODE == 2)
        ? g_scratch[OFF_FS + (size_t)z * NPIX + n0 + nB] : 0.0f;

    float acc[4][4][4];
#pragma unroll
    for (int mt = 0; mt < 4; mt++)
#pragma unroll
        for (int nt = 0; nt < 4; nt++)
#pragma unroll
            for (int r = 0; r < 4; r++) acc[mt][nt][r] = 0.0f;

    float  bv[KPT];
    float  av[8];
    float4 a4[2];

    auto loadStage = [&](int k0) {
#pragma unroll
        for (int j = 0; j < KPT; j++) {
            const size_t gi = (size_t)(k0 + kbB + j) * NPIX + n0 + nB;
            float v;
            if (MODE == 2) {
                v = __ldcs(Xb + gi) * inv_n;
                __stcs(eWrB + gi, v);
            } else {
                v = Xb[gi];
            }
            bv[j] = v;
        }
        if (ACM) {
#pragma unroll
            for (int j = 0; j < 8; j++)
                av[j] = Ab[(size_t)(k0 + kbA + j) * lda + m0 + mA1];
        } else {
            a4[0] = *(const float4*)(Ab + (size_t)(m0 + mA0) * lda + k0 + kshA);
            a4[1] = *(const float4*)(Ab + (size_t)(m0 + mA0) * lda + k0 + kshA + 4);
        }
    };

    auto storeStage = [&]() {
#pragma unroll
        for (int j2 = 0; j2 < KPT / 2; j2++) {
            const float x0 = bv[2 * j2], x1 = bv[2 * j2 + 1];
            const int w = nB * 12 + kbB / 2 + j2;
            Bhw[w] = packbf(x0, x1);
            if (SPLIT == 3) Blw[w] = packbf(x0 - bfhi(x0), x1 - bfhi(x1));
        }
        if (ACM) {
#pragma unroll
            for (int j2 = 0; j2 < 4; j2++) {
                const float x0 = av[2 * j2], x1 = av[2 * j2 + 1];
                const int w = mA1 * 12 + kbA / 2 + j2;
                Ahw[w] = packbf(x0, x1);
                if (SPLIT == 3) Alw[w] = packbf(x0 - bfhi(x0), x1 - bfhi(x1));
            }
        } else {
            const int w = mA0 * 12 + kshA / 2;
            const float xs[8] = {a4[0].x, a4[0].y, a4[0].z, a4[0].w,
                                 a4[1].x, a4[1].y, a4[1].z, a4[1].w};
#pragma unroll
            for (int j2 = 0; j2 < 4; j2++) {
                const float x0 = xs[2 * j2], x1 = xs[2 * j2 + 1];
                Ahw[w + j2] = packbf(x0, x1);
                if (SPLIT == 3) Alw[w + j2] = packbf(x0 - bfhi(x0), x1 - bfhi(x1));
            }
        }
    };

    loadStage(0);

    for (int k0 = 0; k0 < K; k0 += 16) {
        __syncthreads();
        storeStage();
        if (k0 + 16 < K) loadStage(k0 + 16);
        __syncthreads();

        unsigned bhf[4][2], blf[4][2];
#pragma unroll
        for (int p = 0; p < 2; p++) {
            ldsm4(bhf[2 * p][0], bhf[2 * p][1],
                  bhf[2 * p + 1][0], bhf[2 * p + 1][1], bAH[p]);
            if (SPLIT == 3)
                ldsm4(blf[2 * p][0], blf[2 * p][1],
                      blf[2 * p + 1][0], blf[2 * p + 1][1], bAL[p]);
        }
#pragma unroll
        for (int mt = 0; mt < 4; mt++) {
            unsigned ah[4], al[4];
            ldsm4(ah[0], ah[1], ah[2], ah[3], aAH[mt]);
            if (SPLIT == 3) ldsm4(al[0], al[1], al[2], al[3], aAL[mt]);
#pragma unroll
            for (int nt = 0; nt < 4; nt++) {
                if (SPLIT == 3) {
                    MMA_BF16(acc[mt][nt], al, bhf[nt]);
                    MMA_BF16(acc[mt][nt], ah, blf[nt]);
                }
                MMA_BF16(acc[mt][nt], ah, bhf[nt]);
            }
        }
    }

    // ---- epilogue ----
    const float gm = (MODE == 2) ? *gamma : 0.0f;
    const int gid = lane >> 2;
#pragma unroll
    for (int mt = 0; mt < 4; mt++) {
#pragma unroll
        for (int half = 0; half < 2; half++) {
            const int m = m0 + wm + mt * 16 + gid + half * 8;
            float bvv = 0.0f;
            if (MODE == 0 || MODE == 1 || MODE == 4) bvv = bsel[m];
#pragma unroll
            for (int nt = 0; nt < 4; nt++) {
                const int col = n0 + wn + nt * 8 + tig * 2;
                float v0 = acc[mt][nt][half * 2 + 0];
                float v1 = acc[mt][nt][half * 2 + 1];
                if (MODE == 0) {
                    v0 = fmaxf(v0 + bvv, 0.0f);
                    v1 = fmaxf(v1 + bvv, 0.0f);
                } else if (MODE == 1 || MODE == 4) {
                    v0 += bvv;
                    v1 += bvv;
                } else if (MODE == 2) {
                    const float* rp = resAll + (size_t)z * cStride +
                                      (size_t)m * NPIX + col;
                    v0 = fmaf(gm, v0, rp[0]);
                    v1 = fmaf(gm, v1, rp[1]);
                }
                if (MODE == 4) {
                    // pair channel rows (m even) with (m+1): partner in lane+4
                    const float p0 = __shfl_down_sync(0xffffffffu, v0, 4);
                    const float p1 = __shfl_down_sync(0xffffffffu, v1, 4);
                    if ((gid & 1) == 0) {
                        const size_t w0 = (size_t)col * 64 + (m >> 1);
                        PhB[w0]      = packbf(v0, p0);
                        PlB[w0]      = packbf(v0 - bfhi(v0), p0 - bfhi(p0));
                        PhB[w0 + 64] = packbf(v1, p1);
                        PlB[w0 + 64] = packbf(v1 - bfhi(v1), p1 - bfhi(p1));
                    }
                } else {
                    *(float2*)(Cb + (size_t)m * NPIX + col) = make_float2(v0, v1);
                }
            }
        }
    }
}

// ---------------------------------------------------------------------------
// Dedicated attn kernel: e = exp(f^T g), bf16 hi/lo 3-product MMA.
// Pre-packed operands; cp.async 3-stage pipeline, ONE barrier per k-tile.
// Output: fp32 e (streaming stores) -> attn region; per-(slab,col) sums -> PS.
// ---------------------------------------------------------------------------
__global__ __launch_bounds__(512)
void attn_gemm(const unsigned* __restrict__ fh, const unsigned* __restrict__ fl,
               const unsigned* __restrict__ gh, const unsigned* __restrict__ gl,
               float* __restrict__ attnAll)
{
    constexpr int AS = 256 * 12;          // A plane words per stage
    constexpr int BS = 128 * 12;          // B plane words per stage
    constexpr int STW = 2 * AS + 2 * BS;  // stage words
    constexpr int NT  = 8;                // k-tiles (K=128, BK=16)

    extern __shared__ unsigned smw[];
    __shared__ float sstat[4][128];

    const int z = blockIdx.z;
    const unsigned* fhB = fh + (size_t)z * PK_BATCH;
    const unsigned* flB = fl + (size_t)z * PK_BATCH;
    const unsigned* ghB = gh + (size_t)z * PK_BATCH;
    const unsigned* glB = gl + (size_t)z * PK_BATCH;
    float* Cb = attnAll + (size_t)z * (size_t)NPIX * NPIX;

    const int n0 = blockIdx.y * 256;      // attn rows (softmax axis)
    const int c0 = blockIdx.x * 128;      // attn cols
    const int t    = threadIdx.x;
    const int lane = t & 31;
    const int warp = t >> 5;
    const int wm   = (warp >> 2) * 64;
    const int wn   = (warp & 3) * 32;
    const int gid  = lane >> 2;
    const int tig  = lane & 3;

    // cp.async maps
    const int arow = t >> 1, achk = (t & 1) * 4;
    const int brow = (t & 255) >> 1, bchk = (t & 1) * 4, bbuf = t >> 8;
    const unsigned smB = (unsigned)__cvta_generic_to_shared(smw);
    const unsigned dA  = smB + (unsigned)(arow * 12 + achk) * 4u;
    const unsigned dB  = smB + (unsigned)(2 * AS + bbuf * BS +
                                          brow * 12 + bchk) * 4u;
    const unsigned* bSrc = bbuf ? glB : ghB;

    auto issue = [&](int tile) {
        const unsigned so = (unsigned)((tile % 3) * STW) * 4u;
        const int kw = tile * 8;
        cp16(dA + so,            fhB + (size_t)(n0 + arow) * 64 + kw + achk);
        cp16(dA + AS * 4u + so,  flB + (size_t)(n0 + arow) * 64 + kw + achk);
        cp16(dB + so,            bSrc + (size_t)(c0 + brow) * 64 + kw + bchk);
        asm volatile("cp.async.commit_group;");
    };

    // ldmatrix addresses (stage 0 base)
    const int aRow = ((lane >> 3) & 1) * 8 + (lane & 7);
    const int aKh  = (lane >> 4) * 4;
    const int bRow = (lane >> 4) * 8 + (lane & 7);
    const int bKh  = ((lane >> 3) & 1) * 4;
    unsigned aAH[4], aAL[4], bAH[2], bAL[2];
#pragma unroll
    for (int mt = 0; mt < 4; mt++) {
        const unsigned w = (unsigned)((wm + mt * 16 + aRow) * 12 + aKh) * 4u;
        aAH[mt] = smB + w;
        aAL[mt] = smB + AS * 4u + w;
    }
#pragma unroll
    for (int p = 0; p < 2; p++) {
        const unsigned w = (unsigned)((wn + p * 16 + bRow) * 12 + bKh) * 4u;
        bAH[p] = smB + 2u * AS * 4u + w;
        bAL[p] = smB + (2u * AS + BS) * 4u + w;
    }

    float acc[4][4][4];
#pragma unroll
    for (int mt = 0; mt < 4; mt++)
#pragma unroll
        for (int nt = 0; nt < 4; nt++)
#pragma unroll
            for (int r = 0; r < 4; r++) acc[mt][nt][r] = 0.0f;

    // 3-stage pipeline: prologue fills 2 stages; end-of-iter t issues tile
    // t+2 into stage (t+2)%3 = (t-1)%3, whose last reads (iter t-1) are
    // fenced by THIS iter's top barrier -> one __syncthreads per tile.
    issue(0);
    issue(1);

#pragma unroll
    for (int tile = 0; tile < NT; tile++) {
        if (tile < NT - 1) asm volatile("cp.async.wait_group 1;");
        else               asm volatile("cp.async.wait_group 0;");
        __syncthreads();

        const unsigned so = (unsigned)((tile % 3) * STW) * 4u;
        unsigned bhf[4][2], blf[4][2];
#pragma unroll
        for (int p = 0; p < 2; p++) {
            ldsm4(bhf[2 * p][0], bhf[2 * p][1],
                  bhf[2 * p + 1][0], bhf[2 * p + 1][1], bAH[p] + so);
            ldsm4(blf[2 * p][0], blf[2 * p][1],
                  blf[2 * p + 1][0], blf[2 * p + 1][1], bAL[p] + so);
        }
#pragma unroll
        for (int mt = 0; mt < 4; mt++) {
            unsigned ah[4], al[4];
            ldsm4(ah[0], ah[1], ah[2], ah[3], aAH[mt] + so);
            ldsm4(al[0], al[1], al[2], al[3], aAL[mt] + so);
#pragma unroll
            for (int nt = 0; nt < 4; nt++) {
                MMA_BF16(acc[mt][nt], al, bhf[nt]);
                MMA_BF16(acc[mt][nt], ah, blf[nt]);
                MMA_BF16(acc[mt][nt], ah, bhf[nt]);
            }
        }
        if (tile + 2 < NT) issue(tile + 2);
    }

    // ---- epilogue: e = exp(acc), streaming store + column sums ----
    float colsum[8];
#pragma unroll
    for (int j = 0; j < 8; j++) colsum[j] = 0.0f;
#pragma unroll
    for (int mt = 0; mt < 4; mt++) {
#pragma unroll
        for (int half = 0; half < 2; half++) {
            const int m = n0 + wm + mt * 16 + gid + half * 8;
#pragma unroll
            for (int nt = 0; nt < 4; nt++) {
                const int col = c0 + wn + nt * 8 + tig * 2;
                const float v0 = __expf(acc[mt][nt][half * 2 + 0]);
                const float v1 = __expf(acc[mt][nt][half * 2 + 1]);
                colsum[nt * 2 + 0] += v0;
                colsum[nt * 2 + 1] += v1;
                __stcs((float2*)(Cb + (size_t)m * NPIX + col),
                       make_float2(v0, v1));
            }
        }
    }
#pragma unroll
    for (int j = 0; j < 8; j++)
#pragma unroll
        for (int o = 4; o < 32; o <<= 1)
            colsum[j] += __shfl_xor_sync(0xffffffffu, colsum[j], o);
    if (lane < 4) {
#pragma unroll
        for (int nt = 0; nt < 4; nt++)
#pragma unroll
            for (int c = 0; c < 2; c++)
                sstat[warp >> 2][wn + nt * 8 + tig * 2 + c] = colsum[nt * 2 + c];
    }
    __syncthreads();
    if (t < 128) {
        float s = sstat[0][t];
#pragma unroll
        for (int r = 1; r < 4; r++) s += sstat[r][t];
        g_scratch[OFF_PS + ((size_t)z * 16 + blockIdx.y) * NPIX + c0 + t] = s;
    }
}

// ---------------------------------------------------------------------------
__global__ void comb_sum()
{
    const int m = blockIdx.x * 256 + threadIdx.x;
    const int b = blockIdx.y;
    float s = 0.0f;
    for (int i = 0; i < 16; i++)
        s += g_scratch[OFF_PS + ((size_t)b * 16 + i) * NPIX + m];
    g_scratch[OFF_FS + (size_t)b * NPIX + m] = 1.0f / s;
}

// ---------------------------------------------------------------------------
extern "C" void kernel_launch(void* const* d_in, const int* in_sizes, int n_in,
                              void* d_out, int out_size)
{
    (void)in_sizes; (void)n_in; (void)out_size;

    const float* x     = (const float*)d_in[0];
    const float* wf1   = (const float*)d_in[1];
    const float* bf1   = (const float*)d_in[2];
    const float* wf2   = (const float*)d_in[3];
    const float* bf2   = (const float*)d_in[4];
    const float* wg1   = (const float*)d_in[5];
    const float* bg1   = (const float*)d_in[6];
    const float* wg2   = (const float*)d_in[7];
    const float* bg2   = (const float*)d_in[8];
    const float* wh    = (const float*)d_in[9];
    const float* bh    = (const float*)d_in[10];
    const float* gamma = (const float*)d_in[11];

    float* out  = (float*)d_out;                       // (B, C, H, W)
    float* attn = out + (size_t)4 * 256 * NPIX;        // (B, N, N)

    float* scratch = nullptr;
    cudaGetSymbolAddress((void**)&scratch, g_scratch);
    float* tbuf  = scratch + OFF_T;
    float* t2buf = scratch + OFF_T2;
    float* hbuf  = scratch + OFF_H;
    unsigned* fh = (unsigned*)(scratch + OFF_F);
    unsigned* fl = fh + PK_PLANE;
    unsigned* gh = (unsigned*)(scratch + OFF_G);
    unsigned* gl = gh + PK_PLANE;

    const size_t sX  = (size_t)256 * NPIX;
    const size_t sCh = (size_t)128 * NPIX;
    const size_t sAt = (size_t)NPIX * NPIX;

    const int sm1_128 = (128 * 12 + 128 * 12) * 4;     // 12 KB
    const int sm3_128 = sm1_128 * 2;                   // 24 KB
    const int sm1_256 = (256 * 12 + 128 * 12) * 4;     // 18 KB
    const int smAttn  = 3 * (2 * 256 * 12 + 2 * 128 * 12) * 4;  // 108 KB

    static int smemSet = 0;
    if (!smemSet) {
        cudaFuncSetAttribute(attn_gemm,
                             cudaFuncAttributeMaxDynamicSharedMemorySize, smAttn);
        smemSet = 1;
    }

    // f1+g1 (dual, relu, 3-split) -> fp32 temps
    mma_gemm<128, 0, 3, 0, 1><<<dim3(32, 2, 4), 256, sm3_128>>>(
        wf1, wg1, 0, 256, x, x, sX, bf1, bg1, nullptr, nullptr,
        tbuf, t2buf, sCh, 256, nullptr, nullptr, nullptr, nullptr, nullptr);

    // f2+g2 (dual, 3-split) -> packed bf16 hi/lo attn operands
    mma_gemm<128, 0, 3, 4, 1><<<dim3(32, 2, 4), 256, sm3_128>>>(
        wf2, wg2, 0, 128, tbuf, t2buf, sCh, bf2, bg2, nullptr, nullptr,
        nullptr, nullptr, 0, 128, nullptr, fh, gh, fl, gl);

    // h projection (single bf16) -> fp32 h
    mma_gemm<256, 0, 1, 1, 0><<<dim3(32, 1, 4), 512, sm1_256>>>(
        wh, nullptr, 0, 256, x, nullptr, sX, bh, nullptr, nullptr, nullptr,
        hbuf, nullptr, sX, 256, nullptr, nullptr, nullptr, nullptr, nullptr);

    // attn: e = exp(f^T g) -> d_out attn region + fused column sums
    attn_gemm<<<dim3(32, 16, 4), 512, smAttn>>>(fh, fl, gh, gl, attn);

    comb_sum<<<dim3(16, 4), 256>>>();

    // final: out = gamma*(h @ attn_soft) + x; B staging scales e by inv[col]
    // and writes normalized attn back in-place (sole-reader blocks, no race)
    mma_gemm<256, 0, 1, 2, 0><<<dim3(32, 1, 4), 512, sm1_256>>>(
        hbuf, nullptr, sX, NPIX, attn, nullptr, sAt, nullptr, nullptr,
        x, gamma, out, nullptr, sX, 4096, attn,
        nullptr, nullptr, nullptr, nullptr);
}

// round 16
// speedup vs baseline: 1.6135x; 1.6135x over previous
#include <cuda_runtime.h>
#include <cuda_bf16.h>
#include <cstdint>

// Problem-fixed shapes: B=4, C=256, Ch=128, H=W=64 -> N=4096
#define NPIX 4096

// ---------------- scratch (no allocations allowed -> __device__ global) ----
#define OFF_T  0
#define OFF_F  2097152
#define OFF_G  4194304
#define OFF_H  6291456
#define OFF_PM 10485760
#define OFF_PS 11010048
#define OFF_FM 11534336
#define OFF_FS 11550720
#define OFF_T2 11567104
#define SCRATCH_FLOATS (11567104 + 2097152)

static __device__ float g_scratch[SCRATCH_FLOATS];

#define PK_BATCH 262144   // 4096*64 words per batch per plane
#define PK_PLANE 1048576  // 4 batches

// ---------------------------------------------------------------------------
__device__ __forceinline__ unsigned packbf(float x, float y) {
    __nv_bfloat162 t = __floats2bfloat162_rn(x, y);   // .x = low half
    return reinterpret_cast<unsigned&>(t);
}
__device__ __forceinline__ float bfhi(float x) {
    return __bfloat162float(__float2bfloat16(x));
}
__device__ __forceinline__ void ldsm4(unsigned& r0, unsigned& r1,
                                      unsigned& r2, unsigned& r3, unsigned a) {
    asm volatile("ldmatrix.sync.aligned.m8n8.x4.shared.b16 {%0,%1,%2,%3}, [%4];"
                 : "=r"(r0), "=r"(r1), "=r"(r2), "=r"(r3) : "r"(a));
}
__device__ __forceinline__ void cp16(unsigned dst, const void* src) {
    asm volatile("cp.async.cg.shared.global [%0], [%1], 16;"
                 :: "r"(dst), "l"(src));
}

#define MMA_BF16(c, a, b)                                                    \
    asm volatile(                                                            \
        "mma.sync.aligned.m16n8k16.row.col.f32.bf16.bf16.f32 "               \
        "{%0,%1,%2,%3},{%4,%5,%6,%7},{%8,%9},{%0,%1,%2,%3};"                 \
        : "+f"(c[0]), "+f"(c[1]), "+f"(c[2]), "+f"(c[3])                     \
        : "r"(a[0]), "r"(a[1]), "r"(a[2]), "r"(a[3]), "r"(b[0]), "r"(b[1]))

// ---------------------------------------------------------------------------
// Generic bf16 tensor-core GEMM (projections + final).
//   MODE 0: relu(acc+bias)  1: acc+bias
//        2: final (B scaled by inv[col] at staging; normalized writeback to
//           eWr only from blockIdx.y==0; out = gamma*acc + res)
//        4: bias-add then write packed bf16 hi/lo pair-words (attn operands)
// ---------------------------------------------------------------------------
template <int BM, int ACM, int SPLIT, int MODE, int DUAL>
__global__ __launch_bounds__(BM * 2)
void mma_gemm(const float* __restrict__ A, const float* __restrict__ A2,
              size_t aStride, int lda,
              const float* __restrict__ X, const float* __restrict__ X2,
              size_t xStride,
              const float* __restrict__ bias, const float* __restrict__ bias2,
              const float* __restrict__ resAll,
              const float* __restrict__ gamma,
              float* __restrict__ C, float* __restrict__ C2,
              size_t cStride, int K,
              float* __restrict__ eWr,
              unsigned* __restrict__ Pkh, unsigned* __restrict__ Pkh2,
              unsigned* __restrict__ Pkl, unsigned* __restrict__ Pkl2)
{
    constexpr int AW = BM * 12;
    constexpr int BW = 128 * 12;
    constexpr int KPT = 1024 / BM;

    extern __shared__ unsigned smw[];
    unsigned* Ahw = smw;
    unsigned* Bhw = smw + AW;
    unsigned* Alw = (SPLIT == 3) ? (smw + AW + BW) : smw;
    unsigned* Blw = (SPLIT == 3) ? (smw + AW + BW + AW) : smw;

    const int z = blockIdx.z;
    const float* Asel = A;
    const float* Xsel = X;
    const float* bsel = bias;
    float*       Csel = C;
    unsigned*    PhSel = Pkh;
    unsigned*    PlSel = Pkl;
    if (DUAL && blockIdx.y == 1) {
        Asel = A2; Xsel = X2; bsel = bias2; Csel = C2; PhSel = Pkh2; PlSel = Pkl2;
    }

    const float* Ab = Asel + (size_t)z * aStride;
    const float* Xb = Xsel + (size_t)z * xStride;
    float*       Cb = Csel ? Csel + (size_t)z * cStride : (float*)nullptr;
    float*       eWrB = (MODE == 2) ? (eWr + (size_t)z * xStride) : (float*)nullptr;
    const bool   doWB = (MODE == 2) && (blockIdx.y == 0);
    unsigned*    PhB = (MODE == 4) ? PhSel + (size_t)z * PK_BATCH : (unsigned*)nullptr;
    unsigned*    PlB = (MODE == 4) ? PlSel + (size_t)z * PK_BATCH : (unsigned*)nullptr;

    const int m0   = DUAL ? 0 : blockIdx.y * BM;
    const int n0   = blockIdx.x * 128;
    const int t    = threadIdx.x;
    const int lane = t & 31;
    const int warp = t >> 5;
    const int wm   = (warp >> 2) * 64;
    const int wn   = (warp & 3) * 32;
    const int tig  = lane & 3;

    const int nB   = t & 127;
    const int kbB  = (t >> 7) * KPT;
    const int mA0  = t >> 1;
    const int kshA = (t & 1) * 8;
    const int mA1  = t & (BM - 1);
    const int kbA  = (t >= BM) ? 8 : 0;

    const unsigned AhB = (unsigned)__cvta_generic_to_shared(Ahw);
    const unsigned AlB = (unsigned)__cvta_generic_to_shared(Alw);
    const unsigned BhB = (unsigned)__cvta_generic_to_shared(Bhw);
    const unsigned BlB = (unsigned)__cvta_generic_to_shared(Blw);
    const int aRow = ((lane >> 3) & 1) * 8 + (lane & 7);
    const int aKh  = (lane >> 4) * 4;
    const int bRow = (lane >> 4) * 8 + (lane & 7);
    const int bKh  = ((lane >> 3) & 1) * 4;
    unsigned aAH[4], aAL[4], bAH[2], bAL[2];
#pragma unroll
    for (int mt = 0; mt < 4; mt++) {
        const unsigned w = (unsigned)((wm + mt * 16 + aRow) * 12 + aKh) * 4u;
        aAH[mt] = AhB + w;
        aAL[mt] = AlB + w;
    }
#pragma unroll
    for (int p = 0; p < 2; p++) {
        const unsigned w = (unsigned)((wn + p * 16 + bRow) * 12 + bKh) * 4u;
        bAH[p] = BhB + w;
        bAL[p] = BlB + w;
    }

    const float inv_n = (MODE == 2)
        ? g_scratch[OFF_FS + (size_t)z * NPIX + n0 + nB] : 0.0f;

    float acc[4][4][4];
#pragma unroll
    for (int mt = 0; mt < 4; mt++)
#pragma unroll
        for (int nt = 0; nt < 4; nt++)
#pragma unroll
            for (int r = 0; r < 4; r++) acc[mt][nt][r] = 0.0f;

    float  bv[KPT];
    float  av[8];
    float4 a4[2];

    auto loadStage = [&](int k0) {
#pragma unroll
        for (int j = 0; j < KPT; j++) {
            const size_t gi = (size_t)(k0 + kbB + j) * NPIX + n0 + nB;
            float v = Xb[gi];
            if (MODE == 2) {
                v *= inv_n;
                if (doWB) eWrB[gi] = v;
            }
            bv[j] = v;
        }
        if (ACM) {
#pragma unroll
            for (int j = 0; j < 8; j++)
                av[j] = Ab[(size_t)(k0 + kbA + j) * lda + m0 + mA1];
        } else {
            a4[0] = *(const float4*)(Ab + (size_t)(m0 + mA0) * lda + k0 + kshA);
            a4[1] = *(const float4*)(Ab + (size_t)(m0 + mA0) * lda + k0 + kshA + 4);
        }
    };

    auto storeStage = [&]() {
#pragma unroll
        for (int j2 = 0; j2 < KPT / 2; j2++) {
            const float x0 = bv[2 * j2], x1 = bv[2 * j2 + 1];
            const int w = nB * 12 + kbB / 2 + j2;
            Bhw[w] = packbf(x0, x1);
            if (SPLIT == 3) Blw[w] = packbf(x0 - bfhi(x0), x1 - bfhi(x1));
        }
        if (ACM) {
#pragma unroll
            for (int j2 = 0; j2 < 4; j2++) {
                const float x0 = av[2 * j2], x1 = av[2 * j2 + 1];
                const int w = mA1 * 12 + kbA / 2 + j2;
                Ahw[w] = packbf(x0, x1);
                if (SPLIT == 3) Alw[w] = packbf(x0 - bfhi(x0), x1 - bfhi(x1));
            }
        } else {
            const int w = mA0 * 12 + kshA / 2;
            const float xs[8] = {a4[0].x, a4[0].y, a4[0].z, a4[0].w,
                                 a4[1].x, a4[1].y, a4[1].z, a4[1].w};
#pragma unroll
            for (int j2 = 0; j2 < 4; j2++) {
                const float x0 = xs[2 * j2], x1 = xs[2 * j2 + 1];
                Ahw[w + j2] = packbf(x0, x1);
                if (SPLIT == 3) Alw[w + j2] = packbf(x0 - bfhi(x0), x1 - bfhi(x1));
            }
        }
    };

    loadStage(0);

    for (int k0 = 0; k0 < K; k0 += 16) {
        __syncthreads();
        storeStage();
        if (k0 + 16 < K) loadStage(k0 + 16);
        __syncthreads();

        unsigned bhf[4][2], blf[4][2];
#pragma unroll
        for (int p = 0; p < 2; p++) {
            ldsm4(bhf[2 * p][0], bhf[2 * p][1],
                  bhf[2 * p + 1][0], bhf[2 * p + 1][1], bAH[p]);
            if (SPLIT == 3)
                ldsm4(blf[2 * p][0], blf[2 * p][1],
                      blf[2 * p + 1][0], blf[2 * p + 1][1], bAL[p]);
        }
#pragma unroll
        for (int mt = 0; mt < 4; mt++) {
            unsigned ah[4], al[4];
            ldsm4(ah[0], ah[1], ah[2], ah[3], aAH[mt]);
            if (SPLIT == 3) ldsm4(al[0], al[1], al[2], al[3], aAL[mt]);
#pragma unroll
            for (int nt = 0; nt < 4; nt++) {
                if (SPLIT == 3) {
                    MMA_BF16(acc[mt][nt], al, bhf[nt]);
                    MMA_BF16(acc[mt][nt], ah, blf[nt]);
                }
                MMA_BF16(acc[mt][nt], ah, bhf[nt]);
            }
        }
    }

    // ---- epilogue ----
    const float gm = (MODE == 2) ? *gamma : 0.0f;
    const int gid = lane >> 2;
#pragma unroll
    for (int mt = 0; mt < 4; mt++) {
#pragma unroll
        for (int half = 0; half < 2; half++) {
            const int m = m0 + wm + mt * 16 + gid + half * 8;
            float bvv = 0.0f;
            if (MODE == 0 || MODE == 1 || MODE == 4) bvv = bsel[m];
#pragma unroll
            for (int nt = 0; nt < 4; nt++) {
                const int col = n0 + wn + nt * 8 + tig * 2;
                float v0 = acc[mt][nt][half * 2 + 0];
                float v1 = acc[mt][nt][half * 2 + 1];
                if (MODE == 0) {
                    v0 = fmaxf(v0 + bvv, 0.0f);
                    v1 = fmaxf(v1 + bvv, 0.0f);
                } else if (MODE == 1 || MODE == 4) {
                    v0 += bvv;
                    v1 += bvv;
                } else if (MODE == 2) {
                    const float* rp = resAll + (size_t)z * cStride +
                                      (size_t)m * NPIX + col;
                    v0 = fmaf(gm, v0, rp[0]);
                    v1 = fmaf(gm, v1, rp[1]);
                }
                if (MODE == 4) {
                    // pair channel rows (m even) with (m+1): partner in lane+4
                    const float p0 = __shfl_down_sync(0xffffffffu, v0, 4);
                    const float p1 = __shfl_down_sync(0xffffffffu, v1, 4);
                    if ((gid & 1) == 0) {
                        const size_t w0 = (size_t)col * 64 + (m >> 1);
                        PhB[w0]      = packbf(v0, p0);
                        PlB[w0]      = packbf(v0 - bfhi(v0), p0 - bfhi(p0));
                        PhB[w0 + 64] = packbf(v1, p1);
                        PlB[w0 + 64] = packbf(v1 - bfhi(v1), p1 - bfhi(p1));
                    }
                } else {
                    *(float2*)(Cb + (size_t)m * NPIX + col) = make_float2(v0, v1);
                }
            }
        }
    }
}

// ---------------------------------------------------------------------------
// Dedicated attn kernel: e = exp(f^T g), bf16 hi/lo 3-product MMA.
// Pre-packed operands; cp.async 3-stage pipeline, ONE barrier per k-tile.
// ---------------------------------------------------------------------------
__global__ __launch_bounds__(512)
void attn_gemm(const unsigned* __restrict__ fh, const unsigned* __restrict__ fl,
               const unsigned* __restrict__ gh, const unsigned* __restrict__ gl,
               float* __restrict__ attnAll)
{
    constexpr int AS = 256 * 12;          // A plane words per stage
    constexpr int BS = 128 * 12;          // B plane words per stage
    constexpr int STW = 2 * AS + 2 * BS;  // stage words
    constexpr int NT  = 8;                // k-tiles (K=128, BK=16)

    extern __shared__ unsigned smw[];
    __shared__ float sstat[4][128];

    const int z = blockIdx.z;
    const unsigned* fhB = fh + (size_t)z * PK_BATCH;
    const unsigned* flB = fl + (size_t)z * PK_BATCH;
    const unsigned* ghB = gh + (size_t)z * PK_BATCH;
    const unsigned* glB = gl + (size_t)z * PK_BATCH;
    float* Cb = attnAll + (size_t)z * (size_t)NPIX * NPIX;

    const int n0 = blockIdx.y * 256;      // attn rows (softmax axis)
    const int c0 = blockIdx.x * 128;      // attn cols
    const int t    = threadIdx.x;
    const int lane = t & 31;
    const int warp = t >> 5;
    const int wm   = (warp >> 2) * 64;
    const int wn   = (warp & 3) * 32;
    const int gid  = lane >> 2;
    const int tig  = lane & 3;

    // cp.async maps
    const int arow = t >> 1, achk = (t & 1) * 4;
    const int brow = (t & 255) >> 1, bchk = (t & 1) * 4, bbuf = t >> 8;
    const unsigned smB = (unsigned)__cvta_generic_to_shared(smw);
    const unsigned dA  = smB + (unsigned)(arow * 12 + achk) * 4u;
    const unsigned dB  = smB + (unsigned)(2 * AS + bbuf * BS +
                                          brow * 12 + bchk) * 4u;
    const unsigned* bSrc = bbuf ? glB : ghB;

    auto issue = [&](int tile) {
        const unsigned so = (unsigned)((tile % 3) * STW) * 4u;
        const int kw = tile * 8;
        cp16(dA + so,            fhB + (size_t)(n0 + arow) * 64 + kw + achk);
        cp16(dA + AS * 4u + so,  flB + (size_t)(n0 + arow) * 64 + kw + achk);
        cp16(dB + so,            bSrc + (size_t)(c0 + brow) * 64 + kw + bchk);
        asm volatile("cp.async.commit_group;");
    };

    const int aRow = ((lane >> 3) & 1) * 8 + (lane & 7);
    const int aKh  = (lane >> 4) * 4;
    const int bRow = (lane >> 4) * 8 + (lane & 7);
    const int bKh  = ((lane >> 3) & 1) * 4;
    unsigned aAH[4], aAL[4], bAH[2], bAL[2];
#pragma unroll
    for (int mt = 0; mt < 4; mt++) {
        const unsigned w = (unsigned)((wm + mt * 16 + aRow) * 12 + aKh) * 4u;
        aAH[mt] = smB + w;
        aAL[mt] = smB + AS * 4u + w;
    }
#pragma unroll
    for (int p = 0; p < 2; p++) {
        const unsigned w = (unsigned)((wn + p * 16 + bRow) * 12 + bKh) * 4u;
        bAH[p] = smB + 2u * AS * 4u + w;
        bAL[p] = smB + (2u * AS + BS) * 4u + w;
    }

    float acc[4][4][4];
#pragma unroll
    for (int mt = 0; mt < 4; mt++)
#pragma unroll
        for (int nt = 0; nt < 4; nt++)
#pragma unroll
            for (int r = 0; r < 4; r++) acc[mt][nt][r] = 0.0f;

    issue(0);
    issue(1);

#pragma unroll
    for (int tile = 0; tile < NT; tile++) {
        if (tile < NT - 1) asm volatile("cp.async.wait_group 1;");
        else               asm volatile("cp.async.wait_group 0;");
        __syncthreads();

        const unsigned so = (unsigned)((tile % 3) * STW) * 4u;
        unsigned bhf[4][2], blf[4][2];
#pragma unroll
        for (int p = 0; p < 2; p++) {
            ldsm4(bhf[2 * p][0], bhf[2 * p][1],
                  bhf[2 * p + 1][0], bhf[2 * p + 1][1], bAH[p] + so);
            ldsm4(blf[2 * p][0], blf[2 * p][1],
                  blf[2 * p + 1][0], blf[2 * p + 1][1], bAL[p] + so);
        }
#pragma unroll
        for (int mt = 0; mt < 4; mt++) {
            unsigned ah[4], al[4];
            ldsm4(ah[0], ah[1], ah[2], ah[3], aAH[mt] + so);
            ldsm4(al[0], al[1], al[2], al[3], aAL[mt] + so);
#pragma unroll
            for (int nt = 0; nt < 4; nt++) {
                MMA_BF16(acc[mt][nt], al, bhf[nt]);
                MMA_BF16(acc[mt][nt], ah, blf[nt]);
                MMA_BF16(acc[mt][nt], ah, bhf[nt]);
            }
        }
        if (tile + 2 < NT) issue(tile + 2);
    }

    // ---- epilogue: e = exp(acc), store + column sums ----
    float colsum[8];
#pragma unroll
    for (int j = 0; j < 8; j++) colsum[j] = 0.0f;
#pragma unroll
    for (int mt = 0; mt < 4; mt++) {
#pragma unroll
        for (int half = 0; half < 2; half++) {
            const int m = n0 + wm + mt * 16 + gid + half * 8;
#pragma unroll
            for (int nt = 0; nt < 4; nt++) {
                const int col = c0 + wn + nt * 8 + tig * 2;
                const float v0 = __expf(acc[mt][nt][half * 2 + 0]);
                const float v1 = __expf(acc[mt][nt][half * 2 + 1]);
                colsum[nt * 2 + 0] += v0;
                colsum[nt * 2 + 1] += v1;
                *(float2*)(Cb + (size_t)m * NPIX + col) = make_float2(v0, v1);
            }
        }
    }
#pragma unroll
    for (int j = 0; j < 8; j++)
#pragma unroll
        for (int o = 4; o < 32; o <<= 1)
            colsum[j] += __shfl_xor_sync(0xffffffffu, colsum[j], o);
    if (lane < 4) {
#pragma unroll
        for (int nt = 0; nt < 4; nt++)
#pragma unroll
            for (int c = 0; c < 2; c++)
                sstat[warp >> 2][wn + nt * 8 + tig * 2 + c] = colsum[nt * 2 + c];
    }
    __syncthreads();
    if (t < 128) {
        float s = sstat[0][t];
#pragma unroll
        for (int r = 1; r < 4; r++) s += sstat[r][t];
        g_scratch[OFF_PS + ((size_t)z * 16 + blockIdx.y) * NPIX + c0 + t] = s;
    }
}

// ---------------------------------------------------------------------------
__global__ void comb_sum()
{
    const int m = blockIdx.x * 256 + threadIdx.x;
    const int b = blockIdx.y;
    float s = 0.0f;
    for (int i = 0; i < 16; i++)
        s += g_scratch[OFF_PS + ((size_t)b * 16 + i) * NPIX + m];
    g_scratch[OFF_FS + (size_t)b * NPIX + m] = 1.0f / s;
}

// ---------------------------------------------------------------------------
extern "C" void kernel_launch(void* const* d_in, const int* in_sizes, int n_in,
                              void* d_out, int out_size)
{
    (void)in_sizes; (void)n_in; (void)out_size;

    const float* x     = (const float*)d_in[0];
    const float* wf1   = (const float*)d_in[1];
    const float* bf1   = (const float*)d_in[2];
    const float* wf2   = (const float*)d_in[3];
    const float* bf2   = (const float*)d_in[4];
    const float* wg1   = (const float*)d_in[5];
    const float* bg1   = (const float*)d_in[6];
    const float* wg2   = (const float*)d_in[7];
    const float* bg2   = (const float*)d_in[8];
    const float* wh    = (const float*)d_in[9];
    const float* bh    = (const float*)d_in[10];
    const float* gamma = (const float*)d_in[11];

    float* out  = (float*)d_out;                       // (B, C, H, W)
    float* attn = out + (size_t)4 * 256 * NPIX;        // (B, N, N)

    float* scratch = nullptr;
    cudaGetSymbolAddress((void**)&scratch, g_scratch);
    float* tbuf  = scratch + OFF_T;
    float* t2buf = scratch + OFF_T2;
    float* hbuf  = scratch + OFF_H;
    unsigned* fh = (unsigned*)(scratch + OFF_F);
    unsigned* fl = fh + PK_PLANE;
    unsigned* gh = (unsigned*)(scratch + OFF_G);
    unsigned* gl = gh + PK_PLANE;

    const size_t sX  = (size_t)256 * NPIX;
    const size_t sCh = (size_t)128 * NPIX;
    const size_t sAt = (size_t)NPIX * NPIX;

    const int sm1_128 = (128 * 12 + 128 * 12) * 4;     // 12 KB
    const int sm3_128 = sm1_128 * 2;                   // 24 KB
    const int sm1_256 = (256 * 12 + 128 * 12) * 4;     // 18 KB
    const int smAttn  = 3 * (2 * 256 * 12 + 2 * 128 * 12) * 4;  // 108 KB

    static int smemSet = 0;
    if (!smemSet) {
        cudaFuncSetAttribute(attn_gemm,
                             cudaFuncAttributeMaxDynamicSharedMemorySize, smAttn);
        smemSet = 1;
    }

    // f1+g1 (dual, relu, 3-split) -> fp32 temps
    mma_gemm<128, 0, 3, 0, 1><<<dim3(32, 2, 4), 256, sm3_128>>>(
        wf1, wg1, 0, 256, x, x, sX, bf1, bg1, nullptr, nullptr,
        tbuf, t2buf, sCh, 256, nullptr, nullptr, nullptr, nullptr, nullptr);

    // f2+g2 (dual, 3-split) -> packed bf16 hi/lo attn operands
    mma_gemm<128, 0, 3, 4, 1><<<dim3(32, 2, 4), 256, sm3_128>>>(
        wf2, wg2, 0, 128, tbuf, t2buf, sCh, bf2, bg2, nullptr, nullptr,
        nullptr, nullptr, 0, 128, nullptr, fh, gh, fl, gl);

    // h projection (single bf16) -> fp32 h
    mma_gemm<256, 0, 1, 1, 0><<<dim3(32, 1, 4), 512, sm1_256>>>(
        wh, nullptr, 0, 256, x, nullptr, sX, bh, nullptr, nullptr, nullptr,
        hbuf, nullptr, sX, 256, nullptr, nullptr, nullptr, nullptr, nullptr);

    // attn: e = exp(f^T g) -> d_out attn region + fused column sums
    attn_gemm<<<dim3(32, 16, 4), 512, smAttn>>>(fh, fl, gh, gl, attn);

    comb_sum<<<dim3(16, 4), 256>>>();

    // final: out = gamma*(h @ attn_soft) + x; BM=128 x 2 y-blocks -> 2 CTA/SM;
    // normalized attn writeback only from blockIdx.y==0 (sole writer).
    mma_gemm<128, 0, 1, 2, 0><<<dim3(32, 2, 4), 256, sm1_128>>>(
        hbuf, nullptr, sX, NPIX, attn, nullptr, sAt, nullptr, nullptr,
        x, gamma, out, nullptr, sX, 4096, attn,
        nullptr, nullptr, nullptr, nullptr);
}

// round 17
// speedup vs baseline: 1.6165x; 1.0019x over previous
#include <cuda_runtime.h>
#include <cuda_bf16.h>
#include <cstdint>

// Problem-fixed shapes: B=4, C=256, Ch=128, H=W=64 -> N=4096
#define NPIX 4096

// ---------------- scratch (no allocations allowed -> __device__ global) ----
#define OFF_T  0
#define OFF_F  2097152
#define OFF_G  4194304
#define OFF_H  6291456
#define OFF_PM 10485760
#define OFF_PS 11010048
#define OFF_FM 11534336
#define OFF_FS 11550720
#define OFF_T2 11567104
#define OFF_E  13664256ull                 // e = exp(logits), 4*4096*4096
#define SCRATCH_FLOATS (13664256ull + 67108864ull)

static __device__ float g_scratch[SCRATCH_FLOATS];

#define PK_BATCH 262144   // 4096*64 words per batch per plane
#define PK_PLANE 1048576  // 4 batches

// ---------------------------------------------------------------------------
__device__ __forceinline__ unsigned packbf(float x, float y) {
    __nv_bfloat162 t = __floats2bfloat162_rn(x, y);   // .x = low half
    return reinterpret_cast<unsigned&>(t);
}
__device__ __forceinline__ float bfhi(float x) {
    return __bfloat162float(__float2bfloat16(x));
}
__device__ __forceinline__ void ldsm4(unsigned& r0, unsigned& r1,
                                      unsigned& r2, unsigned& r3, unsigned a) {
    asm volatile("ldmatrix.sync.aligned.m8n8.x4.shared.b16 {%0,%1,%2,%3}, [%4];"
                 : "=r"(r0), "=r"(r1), "=r"(r2), "=r"(r3) : "r"(a));
}
__device__ __forceinline__ void cp16(unsigned dst, const void* src) {
    asm volatile("cp.async.cg.shared.global [%0], [%1], 16;"
                 :: "r"(dst), "l"(src));
}

#define MMA_BF16(c, a, b)                                                    \
    asm volatile(                                                            \
        "mma.sync.aligned.m16n8k16.row.col.f32.bf16.bf16.f32 "               \
        "{%0,%1,%2,%3},{%4,%5,%6,%7},{%8,%9},{%0,%1,%2,%3};"                 \
        : "+f"(c[0]), "+f"(c[1]), "+f"(c[2]), "+f"(c[3])                     \
        : "r"(a[0]), "r"(a[1]), "r"(a[2]), "r"(a[3]), "r"(b[0]), "r"(b[1]))

// ---------------------------------------------------------------------------
// Generic bf16 tensor-core GEMM (projections + final).
//   MODE 0: relu(acc+bias)  1: acc+bias
//        2: final (B = e from read-only E buffer, scaled by inv[col] at
//           staging; blockIdx.y==0 writes normalized value to eWr (d_out
//           attn region, which no block reads); out = gamma*acc + res)
//        4: bias-add then write packed bf16 hi/lo pair-words (attn operands)
// ---------------------------------------------------------------------------
template <int BM, int ACM, int SPLIT, int MODE, int DUAL>
__global__ __launch_bounds__(BM * 2)
void mma_gemm(const float* __restrict__ A, const float* __restrict__ A2,
              size_t aStride, int lda,
              const float* __restrict__ X, const float* __restrict__ X2,
              size_t xStride,
              const float* __restrict__ bias, const float* __restrict__ bias2,
              const float* __restrict__ resAll,
              const float* __restrict__ gamma,
              float* __restrict__ C, float* __restrict__ C2,
              size_t cStride, int K,
              float* __restrict__ eWr,
              unsigned* __restrict__ Pkh, unsigned* __restrict__ Pkh2,
              unsigned* __restrict__ Pkl, unsigned* __restrict__ Pkl2)
{
    constexpr int AW = BM * 12;
    constexpr int BW = 128 * 12;
    constexpr int KPT = 1024 / BM;

    extern __shared__ unsigned smw[];
    unsigned* Ahw = smw;
    unsigned* Bhw = smw + AW;
    unsigned* Alw = (SPLIT == 3) ? (smw + AW + BW) : smw;
    unsigned* Blw = (SPLIT == 3) ? (smw + AW + BW + AW) : smw;

    const int z = blockIdx.z;
    const float* Asel = A;
    const float* Xsel = X;
    const float* bsel = bias;
    float*       Csel = C;
    unsigned*    PhSel = Pkh;
    unsigned*    PlSel = Pkl;
    if (DUAL && blockIdx.y == 1) {
        Asel = A2; Xsel = X2; bsel = bias2; Csel = C2; PhSel = Pkh2; PlSel = Pkl2;
    }

    const float* Ab = Asel + (size_t)z * aStride;
    const float* Xb = Xsel + (size_t)z * xStride;
    float*       Cb = Csel ? Csel + (size_t)z * cStride : (float*)nullptr;
    float*       eWrB = (MODE == 2) ? (eWr + (size_t)z * xStride) : (float*)nullptr;
    const bool   doWB = (MODE == 2) && (blockIdx.y == 0);
    unsigned*    PhB = (MODE == 4) ? PhSel + (size_t)z * PK_BATCH : (unsigned*)nullptr;
    unsigned*    PlB = (MODE == 4) ? PlSel + (size_t)z * PK_BATCH : (unsigned*)nullptr;

    const int m0   = DUAL ? 0 : blockIdx.y * BM;
    const int n0   = blockIdx.x * 128;
    const int t    = threadIdx.x;
    const int lane = t & 31;
    const int warp = t >> 5;
    const int wm   = (warp >> 2) * 64;
    const int wn   = (warp & 3) * 32;
    const int tig  = lane & 3;

    const int nB   = t & 127;
    const int kbB  = (t >> 7) * KPT;
    const int mA0  = t >> 1;
    const int kshA = (t & 1) * 8;
    const int mA1  = t & (BM - 1);
    const int kbA  = (t >= BM) ? 8 : 0;

    const unsigned AhB = (unsigned)__cvta_generic_to_shared(Ahw);
    const unsigned AlB = (unsigned)__cvta_generic_to_shared(Alw);
    const unsigned BhB = (unsigned)__cvta_generic_to_shared(Bhw);
    const unsigned BlB = (unsigned)__cvta_generic_to_shared(Blw);
    const int aRow = ((lane >> 3) & 1) * 8 + (lane & 7);
    const int aKh  = (lane >> 4) * 4;
    const int bRow = (lane >> 4) * 8 + (lane & 7);
    const int bKh  = ((lane >> 3) & 1) * 4;
    unsigned aAH[4], aAL[4], bAH[2], bAL[2];
#pragma unroll
    for (int mt = 0; mt < 4; mt++) {
        const unsigned w = (unsigned)((wm + mt * 16 + aRow) * 12 + aKh) * 4u;
        aAH[mt] = AhB + w;
        aAL[mt] = AlB + w;
    }
#pragma unroll
    for (int p = 0; p < 2; p++) {
        const unsigned w = (unsigned)((wn + p * 16 + bRow) * 12 + bKh) * 4u;
        bAH[p] = BhB + w;
        bAL[p] = BlB + w;
    }

    const float inv_n = (MODE == 2)
        ? g_scratch[OFF_FS + (size_t)z * NPIX + n0 + nB] : 0.0f;

    float acc[4][4][4];
#pragma unroll
    for (int mt = 0; mt < 4; mt++)
#pragma unroll
        for (int nt = 0; nt < 4; nt++)
#pragma unroll
            for (int r = 0; r < 4; r++) acc[mt][nt][r] = 0.0f;

    float  bv[KPT];
    float  av[8];
    float4 a4[2];

    auto loadStage = [&](int k0) {
#pragma unroll
        for (int j = 0; j < KPT; j++) {
            const size_t gi = (size_t)(k0 + kbB + j) * NPIX + n0 + nB;
            float v = Xb[gi];
            if (MODE == 2) {
                v *= inv_n;
                if (doWB) eWrB[gi] = v;
            }
            bv[j] = v;
        }
        if (ACM) {
#pragma unroll
            for (int j = 0; j < 8; j++)
                av[j] = Ab[(size_t)(k0 + kbA + j) * lda + m0 + mA1];
        } else {
            a4[0] = *(const float4*)(Ab + (size_t)(m0 + mA0) * lda + k0 + kshA);
            a4[1] = *(const float4*)(Ab + (size_t)(m0 + mA0) * lda + k0 + kshA + 4);
        }
    };

    auto storeStage = [&]() {
#pragma unroll
        for (int j2 = 0; j2 < KPT / 2; j2++) {
            const float x0 = bv[2 * j2], x1 = bv[2 * j2 + 1];
            const int w = nB * 12 + kbB / 2 + j2;
            Bhw[w] = packbf(x0, x1);
            if (SPLIT == 3) Blw[w] = packbf(x0 - bfhi(x0), x1 - bfhi(x1));
        }
        if (ACM) {
#pragma unroll
            for (int j2 = 0; j2 < 4; j2++) {
                const float x0 = av[2 * j2], x1 = av[2 * j2 + 1];
                const int w = mA1 * 12 + kbA / 2 + j2;
                Ahw[w] = packbf(x0, x1);
                if (SPLIT == 3) Alw[w] = packbf(x0 - bfhi(x0), x1 - bfhi(x1));
            }
        } else {
            const int w = mA0 * 12 + kshA / 2;
            const float xs[8] = {a4[0].x, a4[0].y, a4[0].z, a4[0].w,
                                 a4[1].x, a4[1].y, a4[1].z, a4[1].w};
#pragma unroll
            for (int j2 = 0; j2 < 4; j2++) {
                const float x0 = xs[2 * j2], x1 = xs[2 * j2 + 1];
                Ahw[w + j2] = packbf(x0, x1);
                if (SPLIT == 3) Alw[w + j2] = packbf(x0 - bfhi(x0), x1 - bfhi(x1));
            }
        }
    };

    loadStage(0);

    for (int k0 = 0; k0 < K; k0 += 16) {
        __syncthreads();
        storeStage();
        if (k0 + 16 < K) loadStage(k0 + 16);
        __syncthreads();

        unsigned bhf[4][2], blf[4][2];
#pragma unroll
        for (int p = 0; p < 2; p++) {
            ldsm4(bhf[2 * p][0], bhf[2 * p][1],
                  bhf[2 * p + 1][0], bhf[2 * p + 1][1], bAH[p]);
            if (SPLIT == 3)
                ldsm4(blf[2 * p][0], blf[2 * p][1],
                      blf[2 * p + 1][0], blf[2 * p + 1][1], bAL[p]);
        }
#pragma unroll
        for (int mt = 0; mt < 4; mt++) {
            unsigned ah[4], al[4];
            ldsm4(ah[0], ah[1], ah[2], ah[3], aAH[mt]);
            if (SPLIT == 3) ldsm4(al[0], al[1], al[2], al[3], aAL[mt]);
#pragma unroll
            for (int nt = 0; nt < 4; nt++) {
                if (SPLIT == 3) {
                    MMA_BF16(acc[mt][nt], al, bhf[nt]);
                    MMA_BF16(acc[mt][nt], ah, blf[nt]);
                }
                MMA_BF16(acc[mt][nt], ah, bhf[nt]);
            }
        }
    }

    // ---- epilogue ----
    const float gm = (MODE == 2) ? *gamma : 0.0f;
    const int gid = lane >> 2;
#pragma unroll
    for (int mt = 0; mt < 4; mt++) {
#pragma unroll
        for (int half = 0; half < 2; half++) {
            const int m = m0 + wm + mt * 16 + gid + half * 8;
            float bvv = 0.0f;
            if (MODE == 0 || MODE == 1 || MODE == 4) bvv = bsel[m];
#pragma unroll
            for (int nt = 0; nt < 4; nt++) {
                const int col = n0 + wn + nt * 8 + tig * 2;
                float v0 = acc[mt][nt][half * 2 + 0];
                float v1 = acc[mt][nt][half * 2 + 1];
                if (MODE == 0) {
                    v0 = fmaxf(v0 + bvv, 0.0f);
                    v1 = fmaxf(v1 + bvv, 0.0f);
                } else if (MODE == 1 || MODE == 4) {
                    v0 += bvv;
                    v1 += bvv;
                } else if (MODE == 2) {
                    const float* rp = resAll + (size_t)z * cStride +
                                      (size_t)m * NPIX + col;
                    v0 = fmaf(gm, v0, rp[0]);
                    v1 = fmaf(gm, v1, rp[1]);
                }
                if (MODE == 4) {
                    // pair channel rows (m even) with (m+1): partner in lane+4
                    const float p0 = __shfl_down_sync(0xffffffffu, v0, 4);
                    const float p1 = __shfl_down_sync(0xffffffffu, v1, 4);
                    if ((gid & 1) == 0) {
                        const size_t w0 = (size_t)col * 64 + (m >> 1);
                        PhB[w0]      = packbf(v0, p0);
                        PlB[w0]      = packbf(v0 - bfhi(v0), p0 - bfhi(p0));
                        PhB[w0 + 64] = packbf(v1, p1);
                        PlB[w0 + 64] = packbf(v1 - bfhi(v1), p1 - bfhi(p1));
                    }
                } else {
                    *(float2*)(Cb + (size_t)m * NPIX + col) = make_float2(v0, v1);
                }
            }
        }
    }
}

// ---------------------------------------------------------------------------
// Dedicated attn kernel: e = exp(f^T g), bf16 hi/lo 3-product MMA.
// Pre-packed operands; cp.async 3-stage pipeline, ONE barrier per k-tile.
// Output: fp32 e -> E scratch buffer; per-(slab,col) sums -> PS.
// ---------------------------------------------------------------------------
__global__ __launch_bounds__(512)
void attn_gemm(const unsigned* __restrict__ fh, const unsigned* __restrict__ fl,
               const unsigned* __restrict__ gh, const unsigned* __restrict__ gl,
               float* __restrict__ eAll)
{
    constexpr int AS = 256 * 12;          // A plane words per stage
    constexpr int BS = 128 * 12;          // B plane words per stage
    constexpr int STW = 2 * AS + 2 * BS;  // stage words
    constexpr int NT  = 8;                // k-tiles (K=128, BK=16)

    extern __shared__ unsigned smw[];
    __shared__ float sstat[4][128];

    const int z = blockIdx.z;
    const unsigned* fhB = fh + (size_t)z * PK_BATCH;
    const unsigned* flB = fl + (size_t)z * PK_BATCH;
    const unsigned* ghB = gh + (size_t)z * PK_BATCH;
    const unsigned* glB = gl + (size_t)z * PK_BATCH;
    float* Cb = eAll + (size_t)z * (size_t)NPIX * NPIX;

    const int n0 = blockIdx.y * 256;      // attn rows (softmax axis)
    const int c0 = blockIdx.x * 128;      // attn cols
    const int t    = threadIdx.x;
    const int lane = t & 31;
    const int warp = t >> 5;
    const int wm   = (warp >> 2) * 64;
    const int wn   = (warp & 3) * 32;
    const int gid  = lane >> 2;
    const int tig  = lane & 3;

    // cp.async maps
    const int arow = t >> 1, achk = (t & 1) * 4;
    const int brow = (t & 255) >> 1, bchk = (t & 1) * 4, bbuf = t >> 8;
    const unsigned smB = (unsigned)__cvta_generic_to_shared(smw);
    const unsigned dA  = smB + (unsigned)(arow * 12 + achk) * 4u;
    const unsigned dB  = smB + (unsigned)(2 * AS + bbuf * BS +
                                          brow * 12 + bchk) * 4u;
    const unsigned* bSrc = bbuf ? glB : ghB;

    auto issue = [&](int tile) {
        const unsigned so = (unsigned)((tile % 3) * STW) * 4u;
        const int kw = tile * 8;
        cp16(dA + so,            fhB + (size_t)(n0 + arow) * 64 + kw + achk);
        cp16(dA + AS * 4u + so,  flB + (size_t)(n0 + arow) * 64 + kw + achk);
        cp16(dB + so,            bSrc + (size_t)(c0 + brow) * 64 + kw + bchk);
        asm volatile("cp.async.commit_group;");
    };

    const int aRow = ((lane >> 3) & 1) * 8 + (lane & 7);
    const int aKh  = (lane >> 4) * 4;
    const int bRow = (lane >> 4) * 8 + (lane & 7);
    const int bKh  = ((lane >> 3) & 1) * 4;
    unsigned aAH[4], aAL[4], bAH[2], bAL[2];
#pragma unroll
    for (int mt = 0; mt < 4; mt++) {
        const unsigned w = (unsigned)((wm + mt * 16 + aRow) * 12 + aKh) * 4u;
        aAH[mt] = smB + w;
        aAL[mt] = smB + AS * 4u + w;
    }
#pragma unroll
    for (int p = 0; p < 2; p++) {
        const unsigned w = (unsigned)((wn + p * 16 + bRow) * 12 + bKh) * 4u;
        bAH[p] = smB + 2u * AS * 4u + w;
        bAL[p] = smB + (2u * AS + BS) * 4u + w;
    }

    float acc[4][4][4];
#pragma unroll
    for (int mt = 0; mt < 4; mt++)
#pragma unroll
        for (int nt = 0; nt < 4; nt++)
#pragma unroll
            for (int r = 0; r < 4; r++) acc[mt][nt][r] = 0.0f;

    issue(0);
    issue(1);

#pragma unroll
    for (int tile = 0; tile < NT; tile++) {
        if (tile < NT - 1) asm volatile("cp.async.wait_group 1;");
        else               asm volatile("cp.async.wait_group 0;");
        __syncthreads();

        const unsigned so = (unsigned)((tile % 3) * STW) * 4u;
        unsigned bhf[4][2], blf[4][2];
#pragma unroll
        for (int p = 0; p < 2; p++) {
            ldsm4(bhf[2 * p][0], bhf[2 * p][1],
                  bhf[2 * p + 1][0], bhf[2 * p + 1][1], bAH[p] + so);
            ldsm4(blf[2 * p][0], blf[2 * p][1],
                  blf[2 * p + 1][0], blf[2 * p + 1][1], bAL[p] + so);
        }
#pragma unroll
        for (int mt = 0; mt < 4; mt++) {
            unsigned ah[4], al[4];
            ldsm4(ah[0], ah[1], ah[2], ah[3], aAH[mt] + so);
            ldsm4(al[0], al[1], al[2], al[3], aAL[mt] + so);
#pragma unroll
            for (int nt = 0; nt < 4; nt++) {
                MMA_BF16(acc[mt][nt], al, bhf[nt]);
                MMA_BF16(acc[mt][nt], ah, blf[nt]);
                MMA_BF16(acc[mt][nt], ah, bhf[nt]);
            }
        }
        if (tile + 2 < NT) issue(tile + 2);
    }

    // ---- epilogue: e = exp(acc), store + column sums ----
    float colsum[8];
#pragma unroll
    for (int j = 0; j < 8; j++) colsum[j] = 0.0f;
#pragma unroll
    for (int mt = 0; mt < 4; mt++) {
#pragma unroll
        for (int half = 0; half < 2; half++) {
            const int m = n0 + wm + mt * 16 + gid + half * 8;
#pragma unroll
            for (int nt = 0; nt < 4; nt++) {
                const int col = c0 + wn + nt * 8 + tig * 2;
                const float v0 = __expf(acc[mt][nt][half * 2 + 0]);
                const float v1 = __expf(acc[mt][nt][half * 2 + 1]);
                colsum[nt * 2 + 0] += v0;
                colsum[nt * 2 + 1] += v1;
                *(float2*)(Cb + (size_t)m * NPIX + col) = make_float2(v0, v1);
            }
        }
    }
#pragma unroll
    for (int j = 0; j < 8; j++)
#pragma unroll
        for (int o = 4; o < 32; o <<= 1)
            colsum[j] += __shfl_xor_sync(0xffffffffu, colsum[j], o);
    if (lane < 4) {
#pragma unroll
        for (int nt = 0; nt < 4; nt++)
#pragma unroll
            for (int c = 0; c < 2; c++)
                sstat[warp >> 2][wn + nt * 8 + tig * 2 + c] = colsum[nt * 2 + c];
    }
    __syncthreads();
    if (t < 128) {
        float s = sstat[0][t];
#pragma unroll
        for (int r = 1; r < 4; r++) s += sstat[r][t];
        g_scratch[OFF_PS + ((size_t)z * 16 + blockIdx.y) * NPIX + c0 + t] = s;
    }
}

// ---------------------------------------------------------------------------
__global__ void comb_sum()
{
    const int m = blockIdx.x * 256 + threadIdx.x;
    const int b = blockIdx.y;
    float s = 0.0f;
    for (int i = 0; i < 16; i++)
        s += g_scratch[OFF_PS + ((size_t)b * 16 + i) * NPIX + m];
    g_scratch[OFF_FS + (size_t)b * NPIX + m] = 1.0f / s;
}

// ---------------------------------------------------------------------------
extern "C" void kernel_launch(void* const* d_in, const int* in_sizes, int n_in,
                              void* d_out, int out_size)
{
    (void)in_sizes; (void)n_in; (void)out_size;

    const float* x     = (const float*)d_in[0];
    const float* wf1   = (const float*)d_in[1];
    const float* bf1   = (const float*)d_in[2];
    const float* wf2   = (const float*)d_in[3];
    const float* bf2   = (const float*)d_in[4];
    const float* wg1   = (const float*)d_in[5];
    const float* bg1   = (const float*)d_in[6];
    const float* wg2   = (const float*)d_in[7];
    const float* bg2   = (const float*)d_in[8];
    const float* wh    = (const float*)d_in[9];
    const float* bh    = (const float*)d_in[10];
    const float* gamma = (const float*)d_in[11];

    float* out  = (float*)d_out;                       // (B, C, H, W)
    float* attn = out + (size_t)4 * 256 * NPIX;        // (B, N, N)

    float* scratch = nullptr;
    cudaGetSymbolAddress((void**)&scratch, g_scratch);
    float* tbuf  = scratch + OFF_T;
    float* t2buf = scratch + OFF_T2;
    float* hbuf  = scratch + OFF_H;
    float* ebuf  = scratch + OFF_E;
    unsigned* fh = (unsigned*)(scratch + OFF_F);
    unsigned* fl = fh + PK_PLANE;
    unsigned* gh = (unsigned*)(scratch + OFF_G);
    unsigned* gl = gh + PK_PLANE;

    const size_t sX  = (size_t)256 * NPIX;
    const size_t sCh = (size_t)128 * NPIX;
    const size_t sAt = (size_t)NPIX * NPIX;

    const int sm1_128 = (128 * 12 + 128 * 12) * 4;     // 12 KB
    const int sm3_128 = sm1_128 * 2;                   // 24 KB
    const int sm1_256 = (256 * 12 + 128 * 12) * 4;     // 18 KB
    const int smAttn  = 3 * (2 * 256 * 12 + 2 * 128 * 12) * 4;  // 108 KB

    static int smemSet = 0;
    if (!smemSet) {
        cudaFuncSetAttribute(attn_gemm,
                             cudaFuncAttributeMaxDynamicSharedMemorySize, smAttn);
        smemSet = 1;
    }

    // f1+g1 (dual, relu, 3-split) -> fp32 temps
    mma_gemm<128, 0, 3, 0, 1><<<dim3(32, 2, 4), 256, sm3_128>>>(
        wf1, wg1, 0, 256, x, x, sX, bf1, bg1, nullptr, nullptr,
        tbuf, t2buf, sCh, 256, nullptr, nullptr, nullptr, nullptr, nullptr);

    // f2+g2 (dual, 3-split) -> packed bf16 hi/lo attn operands
    mma_gemm<128, 0, 3, 4, 1><<<dim3(32, 2, 4), 256, sm3_128>>>(
        wf2, wg2, 0, 128, tbuf, t2buf, sCh, bf2, bg2, nullptr, nullptr,
        nullptr, nullptr, 0, 128, nullptr, fh, gh, fl, gl);

    // h projection (single bf16) -> fp32 h
    mma_gemm<256, 0, 1, 1, 0><<<dim3(32, 1, 4), 512, sm1_256>>>(
        wh, nullptr, 0, 256, x, nullptr, sX, bh, nullptr, nullptr, nullptr,
        hbuf, nullptr, sX, 256, nullptr, nullptr, nullptr, nullptr, nullptr);

    // attn: e = exp(f^T g) -> E scratch buffer + fused column sums
    attn_gemm<<<dim3(32, 16, 4), 512, smAttn>>>(fh, fl, gh, gl, ebuf);

    comb_sum<<<dim3(16, 4), 256>>>();

    // final: out = gamma*(h @ attn_soft) + x; B = e (read-only for both
    // y-blocks) scaled by inv[col]; y==0 writes normalized attn to d_out
    // (write-only region -> no race, deterministic).
    mma_gemm<128, 0, 1, 2, 0><<<dim3(32, 2, 4), 256, sm1_128>>>(
        hbuf, nullptr, sX, NPIX, ebuf, nullptr, sAt, nullptr, nullptr,
        x, gamma, out, nullptr, sX, 4096, attn,
        nullptr, nullptr, nullptr, nullptr);
}